// round 3
// baseline (speedup 1.0000x reference)
#include <cuda_runtime.h>
#include <cstdint>

// ---------------- problem constants (shapes are fixed by the dataset) -------
#define NMAX   100000
#define DIN    128
#define DH     128
#define DOUT   64
#define NREL   3

// ---------------- scratch (no allocation allowed -> __device__ globals) -----
__device__ float g_z[(size_t)NMAX * DIN];     // per-relation z = (h)W  (reused layer2, 64-wide)
__device__ float g_h[(size_t)NMAX * DH];      // layer-1 accumulator -> relu -> layer-2 input
__device__ float g_deg[12 * NMAX];            // rsqrt(clamped degree): (layer,rel,dir)

// ---------------- helpers ----------------------------------------------------
__device__ __forceinline__ void red_add_v4(float* p, float4 v) {
    asm volatile("red.global.add.v4.f32 [%0], {%1, %2, %3, %4};"
                 :: "l"(p), "f"(v.x), "f"(v.y), "f"(v.z), "f"(v.w) : "memory");
}

// ---------------- generic zero fill ------------------------------------------
__global__ void zero_kernel(float* __restrict__ p, int n4) {
    int i = blockIdx.x * blockDim.x + threadIdx.x;
    if (i < n4) reinterpret_cast<float4*>(p)[i] = make_float4(0.f, 0.f, 0.f, 0.f);
}

// ---------------- degree counting: blockIdx.y = pair (layer*3 + rel) ---------
__global__ void count_deg_kernel(const int* __restrict__ ei, float* __restrict__ deg,
                                 int E, int M) {
    int p = blockIdx.y;                 // 0..5
    int e = blockIdx.x * blockDim.x + threadIdx.x;
    if (e >= E) return;
    int s = __ldg(ei + (size_t)(p * 2 + 0) * E + e);
    int d = __ldg(ei + (size_t)(p * 2 + 1) * E + e);
    atomicAdd(deg + (size_t)(p * 2 + 0) * M + s, 1.0f);   // out-degree of src
    atomicAdd(deg + (size_t)(p * 2 + 1) * M + d, 1.0f);   // in-degree of dst
}

__global__ void rsqrt_kernel(float* __restrict__ deg, int n) {
    int i = blockIdx.x * blockDim.x + threadIdx.x;
    if (i < n) deg[i] = rsqrtf(fmaxf(deg[i], 1.0f));
}

// ---------------- tiled fp32 GEMM with fused row scaling ---------------------
// C[M,BN] = (A[M,128] @ B[128,BN]) * rs[row]
// BM=128, BK=32, 256 threads, per-thread tile 8 x TN (TN = 8 for BN=128, 4 for BN=64)
template<int BN, int TN>
__global__ __launch_bounds__(256)
void gemm_rowscale(const float* __restrict__ A, const float* __restrict__ B,
                   const float* __restrict__ rs, float* __restrict__ C, int M) {
    constexpr int BM = 128;
    constexpr int BK = 32;
    __shared__ float Xs[BM][BK + 1];      // +1 pad -> conflict-free column reads
    __shared__ float Ws[BK][BN];

    const int tid = threadIdx.x;
    const int tx = tid & 15;              // 16 column groups
    const int ty = tid >> 4;              // 16 row groups
    const int row0 = blockIdx.x * BM;

    float acc[8][TN];
    #pragma unroll
    for (int i = 0; i < 8; i++)
        #pragma unroll
        for (int j = 0; j < TN; j++) acc[i][j] = 0.f;

    for (int kt = 0; kt < 128; kt += BK) {
        // load A tile (128 x 32): 1024 float4 slots, 4 per thread
        #pragma unroll
        for (int i = 0; i < 4; i++) {
            int slot = tid + i * 256;
            int r  = slot >> 3;           // 8 float4 per row
            int c4 = (slot & 7) * 4;
            float4 v = make_float4(0.f, 0.f, 0.f, 0.f);
            int gr = row0 + r;
            if (gr < M) v = *reinterpret_cast<const float4*>(A + (size_t)gr * 128 + kt + c4);
            Xs[r][c4 + 0] = v.x; Xs[r][c4 + 1] = v.y;
            Xs[r][c4 + 2] = v.z; Xs[r][c4 + 3] = v.w;
        }
        // load B tile (32 x BN)
        constexpr int BSLOTS = BK * BN / 4;
        #pragma unroll
        for (int i = 0; i < BSLOTS / 256; i++) {
            int slot = tid + i * 256;
            int r  = slot / (BN / 4);
            int c4 = (slot % (BN / 4)) * 4;
            *reinterpret_cast<float4*>(&Ws[r][c4]) =
                *reinterpret_cast<const float4*>(B + (size_t)(kt + r) * BN + c4);
        }
        __syncthreads();

        #pragma unroll
        for (int kk = 0; kk < BK; kk++) {
            float a[8], b[TN];
            #pragma unroll
            for (int i = 0; i < 8; i++) a[i] = Xs[ty * 8 + i][kk];
            #pragma unroll
            for (int jb = 0; jb < TN / 4; jb++) {
                float4 bv = *reinterpret_cast<const float4*>(&Ws[kk][jb * 64 + tx * 4]);
                b[jb * 4 + 0] = bv.x; b[jb * 4 + 1] = bv.y;
                b[jb * 4 + 2] = bv.z; b[jb * 4 + 3] = bv.w;
            }
            #pragma unroll
            for (int i = 0; i < 8; i++)
                #pragma unroll
                for (int j = 0; j < TN; j++) acc[i][j] += a[i] * b[j];
        }
        __syncthreads();
    }

    // epilogue: scale by rs[row], store
    #pragma unroll
    for (int i = 0; i < 8; i++) {
        int gr = row0 + ty * 8 + i;
        if (gr >= M) continue;
        float s = __ldg(rs + gr);
        #pragma unroll
        for (int jb = 0; jb < TN / 4; jb++) {
            float4 v = make_float4(acc[i][jb * 4 + 0] * s, acc[i][jb * 4 + 1] * s,
                                   acc[i][jb * 4 + 2] * s, acc[i][jb * 4 + 3] * s);
            *reinterpret_cast<float4*>(C + (size_t)gr * BN + jb * 64 + tx * 4) = v;
        }
    }
}

// ---------------- edge scatter: out[dst] += rs_in[dst] * z[src] --------------
// 128-wide: one warp per edge, each lane handles one float4
__global__ __launch_bounds__(256)
void scatter128(const float* __restrict__ z, float* __restrict__ out,
                const int* __restrict__ src, const int* __restrict__ dst,
                const float* __restrict__ rsin, int E) {
    int t = blockIdx.x * blockDim.x + threadIdx.x;
    int e = t >> 5;
    if (e >= E) return;
    int lane = t & 31;
    int s = __ldg(src + e);
    int d = __ldg(dst + e);
    float c = __ldg(rsin + d);
    float4 v = *reinterpret_cast<const float4*>(z + (size_t)s * 128 + lane * 4);
    v.x *= c; v.y *= c; v.z *= c; v.w *= c;
    red_add_v4(out + (size_t)d * 128 + lane * 4, v);
}

// 64-wide: 16 lanes per edge (two edges per warp)
__global__ __launch_bounds__(256)
void scatter64(const float* __restrict__ z, float* __restrict__ out,
               const int* __restrict__ src, const int* __restrict__ dst,
               const float* __restrict__ rsin, int E) {
    int t = blockIdx.x * blockDim.x + threadIdx.x;
    int e = t >> 4;
    if (e >= E) return;
    int lane = t & 15;
    int s = __ldg(src + e);
    int d = __ldg(dst + e);
    float c = __ldg(rsin + d);
    float4 v = *reinterpret_cast<const float4*>(z + (size_t)s * 64 + lane * 4);
    v.x *= c; v.y *= c; v.z *= c; v.w *= c;
    red_add_v4(out + (size_t)d * 64 + lane * 4, v);
}

// ---------------- elementwise epilogues --------------------------------------
__global__ void relu_bias128(float* __restrict__ h, const float* __restrict__ b1, int n) {
    int i = blockIdx.x * blockDim.x + threadIdx.x;
    if (i >= n) return;
    int c = i & 127;
    float b = __ldg(b1 + c) + __ldg(b1 + 128 + c) + __ldg(b1 + 256 + c);
    float v = h[i] + b;
    h[i] = v > 0.f ? v : 0.f;
}

__global__ void bias64(float* __restrict__ o, const float* __restrict__ b2, int n) {
    int i = blockIdx.x * blockDim.x + threadIdx.x;
    if (i >= n) return;
    int c = i & 63;
    o[i] += __ldg(b2 + c) + __ldg(b2 + 64 + c) + __ldg(b2 + 128 + c);
}

// ---------------- orchestration ----------------------------------------------
extern "C" void kernel_launch(void* const* d_in, const int* in_sizes, int n_in,
                              void* d_out, int out_size) {
    const float* x  = (const float*)d_in[0];   // [N,128]
    const float* W1 = (const float*)d_in[1];   // [3,128,128]
    const float* b1 = (const float*)d_in[2];   // [3,128]
    const float* W2 = (const float*)d_in[3];   // [3,128,64]
    const float* b2 = (const float*)d_in[4];   // [3,64]
    const int*   ei = (const int*)d_in[5];     // [2,3,2,E] int32
    float* out = (float*)d_out;                // [N,64]

    const int M = in_sizes[0] / DIN;           // 100000
    const int E = in_sizes[5] / (2 * NREL * 2);// 1600000

    float *z, *h, *deg;
    cudaGetSymbolAddress((void**)&z,   g_z);
    cudaGetSymbolAddress((void**)&h,   g_h);
    cudaGetSymbolAddress((void**)&deg, g_deg);

    const int TB = 256;
    auto blocks = [](long n, int tb) { return (int)((n + tb - 1) / tb); };

    // --- degrees -> rsqrt(clamp(deg,1)) for all 12 (layer,rel,dir) arrays ----
    zero_kernel<<<blocks((long)12 * M / 4, TB), TB>>>(deg, 12 * M / 4);
    {
        dim3 g(blocks(E, TB), 6);
        count_deg_kernel<<<g, TB>>>(ei, deg, E, M);
    }
    rsqrt_kernel<<<blocks((long)12 * M, TB), TB>>>(deg, 12 * M);

    const int gemm_grid = (M + 127) / 128;

    // --- layer 1: h = sum_r  D_in_r^{-1/2} A_r D_out_r^{-1/2} (x W1_r) -------
    zero_kernel<<<blocks((long)M * DH / 4, TB), TB>>>(h, M * DH / 4);
    for (int r = 0; r < NREL; r++) {
        int p = 0 * NREL + r;
        gemm_rowscale<128, 8><<<gemm_grid, 256>>>(
            x, W1 + (size_t)r * DIN * DH, deg + (size_t)(p * 2 + 0) * M, z, M);
        scatter128<<<blocks((long)E * 32, TB), TB>>>(
            z, h,
            ei + (size_t)(p * 2 + 0) * E, ei + (size_t)(p * 2 + 1) * E,
            deg + (size_t)(p * 2 + 1) * M, E);
    }
    relu_bias128<<<blocks((long)M * DH, TB), TB>>>(h, b1, M * DH);

    // --- layer 2: out = sum_r D_in A_r D_out (h W2_r) + sum_r b2_r -----------
    zero_kernel<<<blocks((long)M * DOUT / 4, TB), TB>>>(out, M * DOUT / 4);
    for (int r = 0; r < NREL; r++) {
        int p = 1 * NREL + r;
        gemm_rowscale<64, 4><<<gemm_grid, 256>>>(
            h, W2 + (size_t)r * DH * DOUT, deg + (size_t)(p * 2 + 0) * M, z, M);
        scatter64<<<blocks((long)E * 16, TB), TB>>>(
            z, out,
            ei + (size_t)(p * 2 + 0) * E, ei + (size_t)(p * 2 + 1) * E,
            deg + (size_t)(p * 2 + 1) * M, E);
    }
    bias64<<<blocks((long)M * DOUT, TB), TB>>>(out, b2, M * DOUT);
}

// round 4
// speedup vs baseline: 1.4649x; 1.4649x over previous
#include <cuda_runtime.h>
#include <cstdint>

// ---------------- problem constants ------------------------------------------
#define NMAX   100000
#define EMAX   1600000
#define DIN    128
#define DH     128
#define DOUT   64
#define NREL   3
#define NPAIR  6                     // (layer, relation) pairs
#define SCAN_CHUNK 1024              // elements per scan block
#define MAXBLK 128                   // >= ceil(NMAX/SCAN_CHUNK) = 98

// ---------------- scratch (__device__ globals; no allocation allowed) --------
__device__ float g_z[(size_t)NMAX * DIN];          // per-relation z = h @ W (scaled)
__device__ float g_h[(size_t)NMAX * DH];           // layer-1 accumulator
__device__ int   g_degi[12 * NMAX];                // int degrees: (pair,dir)
__device__ float g_degf[12 * NMAX];                // rsqrt(clamp(deg,1))
__device__ int   g_off [NPAIR * NMAX];             // CSR offsets (by dst) per pair
__device__ int   g_cnt [NPAIR * NMAX];             // fill tickets
__device__ int   g_adj [(size_t)NPAIR * EMAX];     // src ids grouped by dst
__device__ int   g_bsum[NPAIR * MAXBLK];           // scan block partials

// ---------------- degree counting (int), grid.y = pair -----------------------
__global__ void count_deg_kernel(const int* __restrict__ ei, int* __restrict__ degi,
                                 int E, int M) {
    int p = blockIdx.y;
    int e = blockIdx.x * blockDim.x + threadIdx.x;
    if (e >= E) return;
    int s = __ldg(ei + (size_t)(p * 2 + 0) * E + e);
    int d = __ldg(ei + (size_t)(p * 2 + 1) * E + e);
    atomicAdd(degi + (size_t)(p * 2 + 0) * M + s, 1);
    atomicAdd(degi + (size_t)(p * 2 + 1) * M + d, 1);
}

__global__ void rsqrt_kernel(const int* __restrict__ degi, float* __restrict__ degf, int n) {
    int i = blockIdx.x * blockDim.x + threadIdx.x;
    if (i < n) degf[i] = rsqrtf((float)max(degi[i], 1));
}

// ---------------- exclusive scan of in-degrees -> CSR offsets ----------------
// Phase A: per-chunk exclusive scan + block totals.
__global__ __launch_bounds__(256)
void scanA(const int* __restrict__ degi, int* __restrict__ off,
           int* __restrict__ bsum, int M) {
    int p = blockIdx.y;
    const int* deg = degi + (size_t)(p * 2 + 1) * M;   // in-degree array of pair p
    int* o = off + (size_t)p * M;
    int base = blockIdx.x * SCAN_CHUNK;
    int tid = threadIdx.x;

    int v[4];
    int t = 0;
    #pragma unroll
    for (int k = 0; k < 4; k++) {
        int idx = base + tid * 4 + k;
        v[k] = (idx < M) ? deg[idx] : 0;
        t += v[k];
    }
    __shared__ int sm[256];
    sm[tid] = t;
    __syncthreads();
    #pragma unroll
    for (int ofs = 1; ofs < 256; ofs <<= 1) {
        int u = (tid >= ofs) ? sm[tid - ofs] : 0;
        __syncthreads();
        sm[tid] += u;
        __syncthreads();
    }
    int ex = sm[tid] - t;            // exclusive prefix of this thread's 4-group
    int run = ex;
    #pragma unroll
    for (int k = 0; k < 4; k++) {
        int idx = base + tid * 4 + k;
        if (idx < M) o[idx] = run;
        run += v[k];
    }
    if (tid == 255) bsum[p * MAXBLK + blockIdx.x] = sm[255];
}

// Phase B: exclusive scan of block totals (one block per pair).
__global__ __launch_bounds__(MAXBLK)
void scanB(int* __restrict__ bsum, int nblk) {
    int p = blockIdx.x;
    int tid = threadIdx.x;
    int* b = bsum + p * MAXBLK;
    int t = (tid < nblk) ? b[tid] : 0;
    __shared__ int sm[MAXBLK];
    sm[tid] = t;
    __syncthreads();
    #pragma unroll
    for (int ofs = 1; ofs < MAXBLK; ofs <<= 1) {
        int u = (tid >= ofs) ? sm[tid - ofs] : 0;
        __syncthreads();
        sm[tid] += u;
        __syncthreads();
    }
    if (tid < nblk) b[tid] = sm[tid] - t;
}

// Phase C: add scanned block bases.
__global__ void scanC(int* __restrict__ off, const int* __restrict__ bsum, int M) {
    int p = blockIdx.y;
    int i = blockIdx.x * blockDim.x + threadIdx.x;
    if (i < M) off[(size_t)p * M + i] += bsum[p * MAXBLK + (i >> 10)];
}

// ---------------- CSR fill: adj grouped by dst --------------------------------
__global__ void fill_adj_kernel(const int* __restrict__ ei, const int* __restrict__ off,
                                int* __restrict__ cnt, int* __restrict__ adj,
                                int E, int M) {
    int p = blockIdx.y;
    int e = blockIdx.x * blockDim.x + threadIdx.x;
    if (e >= E) return;
    int s = __ldg(ei + (size_t)(p * 2 + 0) * E + e);
    int d = __ldg(ei + (size_t)(p * 2 + 1) * E + e);
    int pos = atomicAdd(cnt + (size_t)p * M + d, 1);
    adj[(size_t)p * E + off[(size_t)p * M + d] + pos] = s;
}

// ---------------- tiled fp32 GEMM with fused row scaling ---------------------
template<int BN, int TN>
__global__ __launch_bounds__(256)
void gemm_rowscale(const float* __restrict__ A, const float* __restrict__ B,
                   const float* __restrict__ rs, float* __restrict__ C, int M) {
    constexpr int BM = 128;
    constexpr int BK = 32;
    __shared__ float Xs[BM][BK + 1];
    __shared__ float Ws[BK][BN];

    const int tid = threadIdx.x;
    const int tx = tid & 15;
    const int ty = tid >> 4;
    const int row0 = blockIdx.x * BM;

    float acc[8][TN];
    #pragma unroll
    for (int i = 0; i < 8; i++)
        #pragma unroll
        for (int j = 0; j < TN; j++) acc[i][j] = 0.f;

    for (int kt = 0; kt < 128; kt += BK) {
        #pragma unroll
        for (int i = 0; i < 4; i++) {
            int slot = tid + i * 256;
            int r  = slot >> 3;
            int c4 = (slot & 7) * 4;
            float4 v = make_float4(0.f, 0.f, 0.f, 0.f);
            int gr = row0 + r;
            if (gr < M) v = *reinterpret_cast<const float4*>(A + (size_t)gr * 128 + kt + c4);
            Xs[r][c4 + 0] = v.x; Xs[r][c4 + 1] = v.y;
            Xs[r][c4 + 2] = v.z; Xs[r][c4 + 3] = v.w;
        }
        constexpr int BSLOTS = BK * BN / 4;
        #pragma unroll
        for (int i = 0; i < BSLOTS / 256; i++) {
            int slot = tid + i * 256;
            int r  = slot / (BN / 4);
            int c4 = (slot % (BN / 4)) * 4;
            *reinterpret_cast<float4*>(&Ws[r][c4]) =
                *reinterpret_cast<const float4*>(B + (size_t)(kt + r) * BN + c4);
        }
        __syncthreads();

        #pragma unroll
        for (int kk = 0; kk < BK; kk++) {
            float a[8], b[TN];
            #pragma unroll
            for (int i = 0; i < 8; i++) a[i] = Xs[ty * 8 + i][kk];
            #pragma unroll
            for (int jb = 0; jb < TN / 4; jb++) {
                float4 bv = *reinterpret_cast<const float4*>(&Ws[kk][jb * 64 + tx * 4]);
                b[jb * 4 + 0] = bv.x; b[jb * 4 + 1] = bv.y;
                b[jb * 4 + 2] = bv.z; b[jb * 4 + 3] = bv.w;
            }
            #pragma unroll
            for (int i = 0; i < 8; i++)
                #pragma unroll
                for (int j = 0; j < TN; j++) acc[i][j] += a[i] * b[j];
        }
        __syncthreads();
    }

    #pragma unroll
    for (int i = 0; i < 8; i++) {
        int gr = row0 + ty * 8 + i;
        if (gr >= M) continue;
        float s = __ldg(rs + gr);
        #pragma unroll
        for (int jb = 0; jb < TN / 4; jb++) {
            float4 v = make_float4(acc[i][jb * 4 + 0] * s, acc[i][jb * 4 + 1] * s,
                                   acc[i][jb * 4 + 2] * s, acc[i][jb * 4 + 3] * s);
            *reinterpret_cast<float4*>(C + (size_t)gr * BN + jb * 64 + tx * 4) = v;
        }
    }
}

// ---------------- CSR gather aggregation --------------------------------------
// 128-wide: one warp per dst; lane owns float4. out[d] += rs_in[d] * sum z[src].
__global__ __launch_bounds__(256)
void gather128(const float* __restrict__ z, float* __restrict__ out,
               const int* __restrict__ off, const int* __restrict__ degin,
               const int* __restrict__ adj, const float* __restrict__ rsin, int M) {
    int w = (blockIdx.x * blockDim.x + threadIdx.x) >> 5;
    if (w >= M) return;
    int lane = threadIdx.x & 31;
    int st = __ldg(off + w);
    int len = __ldg(degin + w);
    float4 acc = make_float4(0.f, 0.f, 0.f, 0.f);
    int j = 0;
    for (; j + 1 < len; j += 2) {            // 2-deep unroll for MLP
        int s0 = __ldg(adj + st + j);
        int s1 = __ldg(adj + st + j + 1);
        float4 v0 = __ldg(reinterpret_cast<const float4*>(z + (size_t)s0 * 128 + lane * 4));
        float4 v1 = __ldg(reinterpret_cast<const float4*>(z + (size_t)s1 * 128 + lane * 4));
        acc.x += v0.x + v1.x; acc.y += v0.y + v1.y;
        acc.z += v0.z + v1.z; acc.w += v0.w + v1.w;
    }
    if (j < len) {
        int s0 = __ldg(adj + st + j);
        float4 v0 = __ldg(reinterpret_cast<const float4*>(z + (size_t)s0 * 128 + lane * 4));
        acc.x += v0.x; acc.y += v0.y; acc.z += v0.z; acc.w += v0.w;
    }
    float c = __ldg(rsin + w);
    float4* hp = reinterpret_cast<float4*>(out + (size_t)w * 128 + lane * 4);
    float4 cur = *hp;
    cur.x += c * acc.x; cur.y += c * acc.y;
    cur.z += c * acc.z; cur.w += c * acc.w;
    *hp = cur;
}

// 64-wide: one warp per dst; lane owns float2.
__global__ __launch_bounds__(256)
void gather64(const float* __restrict__ z, float* __restrict__ out,
              const int* __restrict__ off, const int* __restrict__ degin,
              const int* __restrict__ adj, const float* __restrict__ rsin, int M) {
    int w = (blockIdx.x * blockDim.x + threadIdx.x) >> 5;
    if (w >= M) return;
    int lane = threadIdx.x & 31;
    int st = __ldg(off + w);
    int len = __ldg(degin + w);
    float2 acc = make_float2(0.f, 0.f);
    int j = 0;
    for (; j + 1 < len; j += 2) {
        int s0 = __ldg(adj + st + j);
        int s1 = __ldg(adj + st + j + 1);
        float2 v0 = __ldg(reinterpret_cast<const float2*>(z + (size_t)s0 * 64 + lane * 2));
        float2 v1 = __ldg(reinterpret_cast<const float2*>(z + (size_t)s1 * 64 + lane * 2));
        acc.x += v0.x + v1.x; acc.y += v0.y + v1.y;
    }
    if (j < len) {
        int s0 = __ldg(adj + st + j);
        float2 v0 = __ldg(reinterpret_cast<const float2*>(z + (size_t)s0 * 64 + lane * 2));
        acc.x += v0.x; acc.y += v0.y;
    }
    float c = __ldg(rsin + w);
    float2* hp = reinterpret_cast<float2*>(out + (size_t)w * 64 + lane * 2);
    float2 cur = *hp;
    cur.x += c * acc.x; cur.y += c * acc.y;
    *hp = cur;
}

// ---------------- elementwise epilogues --------------------------------------
__global__ void relu_bias128(float* __restrict__ h, const float* __restrict__ b1, int n) {
    int i = blockIdx.x * blockDim.x + threadIdx.x;
    if (i >= n) return;
    int c = i & 127;
    float b = __ldg(b1 + c) + __ldg(b1 + 128 + c) + __ldg(b1 + 256 + c);
    float v = h[i] + b;
    h[i] = v > 0.f ? v : 0.f;
}

__global__ void bias64(float* __restrict__ o, const float* __restrict__ b2, int n) {
    int i = blockIdx.x * blockDim.x + threadIdx.x;
    if (i >= n) return;
    int c = i & 63;
    o[i] += __ldg(b2 + c) + __ldg(b2 + 64 + c) + __ldg(b2 + 128 + c);
}

// ---------------- orchestration ----------------------------------------------
extern "C" void kernel_launch(void* const* d_in, const int* in_sizes, int n_in,
                              void* d_out, int out_size) {
    const float* x  = (const float*)d_in[0];
    const float* W1 = (const float*)d_in[1];
    const float* b1 = (const float*)d_in[2];
    const float* W2 = (const float*)d_in[3];
    const float* b2 = (const float*)d_in[4];
    const int*   ei = (const int*)d_in[5];
    float* out = (float*)d_out;

    const int M = in_sizes[0] / DIN;
    const int E = in_sizes[5] / (2 * NREL * 2);

    float *z, *h, *degf;
    int *degi, *off, *cnt, *adj, *bsum;
    cudaGetSymbolAddress((void**)&z,    g_z);
    cudaGetSymbolAddress((void**)&h,    g_h);
    cudaGetSymbolAddress((void**)&degf, g_degf);
    cudaGetSymbolAddress((void**)&degi, g_degi);
    cudaGetSymbolAddress((void**)&off,  g_off);
    cudaGetSymbolAddress((void**)&cnt,  g_cnt);
    cudaGetSymbolAddress((void**)&adj,  g_adj);
    cudaGetSymbolAddress((void**)&bsum, g_bsum);

    const int TB = 256;
    auto blocks = [](long n, int tb) { return (int)((n + tb - 1) / tb); };
    const int nblk_scan = (M + SCAN_CHUNK - 1) / SCAN_CHUNK;

    // --- zero counters / accumulators (memset nodes are graph-capturable) ----
    cudaMemsetAsync(degi, 0, (size_t)12 * M * sizeof(int));
    cudaMemsetAsync(cnt,  0, (size_t)NPAIR * M * sizeof(int));
    cudaMemsetAsync(h,    0, (size_t)M * DH * sizeof(float));
    cudaMemsetAsync(out,  0, (size_t)M * DOUT * sizeof(float));

    // --- degrees + CSR build for all 6 pairs ----------------------------------
    { dim3 g(blocks(E, TB), NPAIR); count_deg_kernel<<<g, TB>>>(ei, degi, E, M); }
    rsqrt_kernel<<<blocks((long)12 * M, TB), TB>>>(degi, degf, 12 * M);
    { dim3 g(nblk_scan, NPAIR); scanA<<<g, 256>>>(degi, off, bsum, M); }
    scanB<<<NPAIR, MAXBLK>>>(bsum, nblk_scan);
    { dim3 g(blocks(M, TB), NPAIR); scanC<<<g, TB>>>(off, bsum, M); }
    { dim3 g(blocks(E, TB), NPAIR); fill_adj_kernel<<<g, TB>>>(ei, off, cnt, adj, E, M); }

    const int gemm_grid = (M + 127) / 128;
    const int gw = blocks((long)M * 32, TB);      // gather grids (warp per node)

    // --- layer 1 ---------------------------------------------------------------
    for (int r = 0; r < NREL; r++) {
        int p = 0 * NREL + r;
        gemm_rowscale<128, 8><<<gemm_grid, 256>>>(
            x, W1 + (size_t)r * DIN * DH, degf + (size_t)(p * 2 + 0) * M, z, M);
        gather128<<<gw, TB>>>(z, h,
            off + (size_t)p * M, degi + (size_t)(p * 2 + 1) * M,
            adj + (size_t)p * E, degf + (size_t)(p * 2 + 1) * M, M);
    }
    relu_bias128<<<blocks((long)M * DH, TB), TB>>>(h, b1, M * DH);

    // --- layer 2 ---------------------------------------------------------------
    for (int r = 0; r < NREL; r++) {
        int p = 1 * NREL + r;
        gemm_rowscale<64, 4><<<gemm_grid, 256>>>(
            h, W2 + (size_t)r * DH * DOUT, degf + (size_t)(p * 2 + 0) * M, z, M);
        gather64<<<gw, TB>>>(z, out,
            off + (size_t)p * M, degi + (size_t)(p * 2 + 1) * M,
            adj + (size_t)p * E, degf + (size_t)(p * 2 + 1) * M, M);
    }
    bias64<<<blocks((long)M * DOUT, TB), TB>>>(out, b2, M * DOUT);
}

// round 5
// speedup vs baseline: 1.4681x; 1.0022x over previous
#include <cuda_runtime.h>
#include <cstdint>

// ---------------- problem constants ------------------------------------------
#define NMAX   100000
#define EMAX   1600000
#define DIN    128
#define DH     128
#define DOUT   64
#define NREL   3
#define NPAIR  6                     // (layer, relation) pairs
#define SCAN_CHUNK 1024              // elements per scan block
#define MAXBLK 128                   // >= ceil(NMAX/SCAN_CHUNK) = 98

// ---------------- scratch (__device__ globals; no allocation allowed) --------
__device__ float g_z[(size_t)NMAX * DIN];          // per-relation z = h @ W (scaled)
__device__ float g_h[(size_t)NMAX * DH];           // layer-1 accumulator
__device__ int   g_degi[12 * NMAX];                // int degrees: (pair,dir)
__device__ float g_degf[12 * NMAX];                // rsqrt(clamp(deg,1))
__device__ int   g_off [NPAIR * NMAX];             // CSR offsets (by dst) per pair
__device__ int   g_cnt [NPAIR * NMAX];             // fill tickets
__device__ int   g_adj [(size_t)NPAIR * EMAX];     // src ids grouped by dst
__device__ int   g_bsum[NPAIR * MAXBLK];           // scan block partials

// ---------------- degree counting (int), grid.y = pair -----------------------
__global__ void count_deg_kernel(const int* __restrict__ ei, int* __restrict__ degi,
                                 int E, int M) {
    int p = blockIdx.y;
    int e = blockIdx.x * blockDim.x + threadIdx.x;
    if (e >= E) return;
    int s = __ldg(ei + (size_t)(p * 2 + 0) * E + e);
    int d = __ldg(ei + (size_t)(p * 2 + 1) * E + e);
    atomicAdd(degi + (size_t)(p * 2 + 0) * M + s, 1);
    atomicAdd(degi + (size_t)(p * 2 + 1) * M + d, 1);
}

__global__ void rsqrt_kernel(const int* __restrict__ degi, float* __restrict__ degf, int n) {
    int i = blockIdx.x * blockDim.x + threadIdx.x;
    if (i < n) degf[i] = rsqrtf((float)max(degi[i], 1));
}

// ---------------- exclusive scan of in-degrees -> CSR offsets ----------------
// Phase A: per-chunk exclusive scan + block totals.
__global__ __launch_bounds__(256)
void scanA(const int* __restrict__ degi, int* __restrict__ off,
           int* __restrict__ bsum, int M) {
    int p = blockIdx.y;
    const int* deg = degi + (size_t)(p * 2 + 1) * M;   // in-degree array of pair p
    int* o = off + (size_t)p * M;
    int base = blockIdx.x * SCAN_CHUNK;
    int tid = threadIdx.x;

    int v[4];
    int t = 0;
    #pragma unroll
    for (int k = 0; k < 4; k++) {
        int idx = base + tid * 4 + k;
        v[k] = (idx < M) ? deg[idx] : 0;
        t += v[k];
    }
    __shared__ int sm[256];
    sm[tid] = t;
    __syncthreads();
    #pragma unroll
    for (int ofs = 1; ofs < 256; ofs <<= 1) {
        int u = (tid >= ofs) ? sm[tid - ofs] : 0;
        __syncthreads();
        sm[tid] += u;
        __syncthreads();
    }
    int ex = sm[tid] - t;            // exclusive prefix of this thread's 4-group
    int run = ex;
    #pragma unroll
    for (int k = 0; k < 4; k++) {
        int idx = base + tid * 4 + k;
        if (idx < M) o[idx] = run;
        run += v[k];
    }
    if (tid == 255) bsum[p * MAXBLK + blockIdx.x] = sm[255];
}

// Phase B: exclusive scan of block totals (one block per pair).
__global__ __launch_bounds__(MAXBLK)
void scanB(int* __restrict__ bsum, int nblk) {
    int p = blockIdx.x;
    int tid = threadIdx.x;
    int* b = bsum + p * MAXBLK;
    int t = (tid < nblk) ? b[tid] : 0;
    __shared__ int sm[MAXBLK];
    sm[tid] = t;
    __syncthreads();
    #pragma unroll
    for (int ofs = 1; ofs < MAXBLK; ofs <<= 1) {
        int u = (tid >= ofs) ? sm[tid - ofs] : 0;
        __syncthreads();
        sm[tid] += u;
        __syncthreads();
    }
    if (tid < nblk) b[tid] = sm[tid] - t;
}

// Phase C: add scanned block bases.
__global__ void scanC(int* __restrict__ off, const int* __restrict__ bsum, int M) {
    int p = blockIdx.y;
    int i = blockIdx.x * blockDim.x + threadIdx.x;
    if (i < M) off[(size_t)p * M + i] += bsum[p * MAXBLK + (i >> 10)];
}

// ---------------- CSR fill: adj grouped by dst --------------------------------
__global__ void fill_adj_kernel(const int* __restrict__ ei, const int* __restrict__ off,
                                int* __restrict__ cnt, int* __restrict__ adj,
                                int E, int M) {
    int p = blockIdx.y;
    int e = blockIdx.x * blockDim.x + threadIdx.x;
    if (e >= E) return;
    int s = __ldg(ei + (size_t)(p * 2 + 0) * E + e);
    int d = __ldg(ei + (size_t)(p * 2 + 1) * E + e);
    int pos = atomicAdd(cnt + (size_t)p * M + d, 1);
    adj[(size_t)p * E + off[(size_t)p * M + d] + pos] = s;
}

// ---------------- tiled fp32 GEMM with fused row scaling ---------------------
template<int BN, int TN>
__global__ __launch_bounds__(256)
void gemm_rowscale(const float* __restrict__ A, const float* __restrict__ B,
                   const float* __restrict__ rs, float* __restrict__ C, int M) {
    constexpr int BM = 128;
    constexpr int BK = 32;
    __shared__ float Xs[BM][BK + 1];
    __shared__ float Ws[BK][BN];

    const int tid = threadIdx.x;
    const int tx = tid & 15;
    const int ty = tid >> 4;
    const int row0 = blockIdx.x * BM;

    float acc[8][TN];
    #pragma unroll
    for (int i = 0; i < 8; i++)
        #pragma unroll
        for (int j = 0; j < TN; j++) acc[i][j] = 0.f;

    for (int kt = 0; kt < 128; kt += BK) {
        #pragma unroll
        for (int i = 0; i < 4; i++) {
            int slot = tid + i * 256;
            int r  = slot >> 3;
            int c4 = (slot & 7) * 4;
            float4 v = make_float4(0.f, 0.f, 0.f, 0.f);
            int gr = row0 + r;
            if (gr < M) v = *reinterpret_cast<const float4*>(A + (size_t)gr * 128 + kt + c4);
            Xs[r][c4 + 0] = v.x; Xs[r][c4 + 1] = v.y;
            Xs[r][c4 + 2] = v.z; Xs[r][c4 + 3] = v.w;
        }
        constexpr int BSLOTS = BK * BN / 4;
        #pragma unroll
        for (int i = 0; i < BSLOTS / 256; i++) {
            int slot = tid + i * 256;
            int r  = slot / (BN / 4);
            int c4 = (slot % (BN / 4)) * 4;
            *reinterpret_cast<float4*>(&Ws[r][c4]) =
                *reinterpret_cast<const float4*>(B + (size_t)(kt + r) * BN + c4);
        }
        __syncthreads();

        #pragma unroll
        for (int kk = 0; kk < BK; kk++) {
            float a[8], b[TN];
            #pragma unroll
            for (int i = 0; i < 8; i++) a[i] = Xs[ty * 8 + i][kk];
            #pragma unroll
            for (int jb = 0; jb < TN / 4; jb++) {
                float4 bv = *reinterpret_cast<const float4*>(&Ws[kk][jb * 64 + tx * 4]);
                b[jb * 4 + 0] = bv.x; b[jb * 4 + 1] = bv.y;
                b[jb * 4 + 2] = bv.z; b[jb * 4 + 3] = bv.w;
            }
            #pragma unroll
            for (int i = 0; i < 8; i++)
                #pragma unroll
                for (int j = 0; j < TN; j++) acc[i][j] += a[i] * b[j];
        }
        __syncthreads();
    }

    #pragma unroll
    for (int i = 0; i < 8; i++) {
        int gr = row0 + ty * 8 + i;
        if (gr >= M) continue;
        float s = __ldg(rs + gr);
        #pragma unroll
        for (int jb = 0; jb < TN / 4; jb++) {
            float4 v = make_float4(acc[i][jb * 4 + 0] * s, acc[i][jb * 4 + 1] * s,
                                   acc[i][jb * 4 + 2] * s, acc[i][jb * 4 + 3] * s);
            *reinterpret_cast<float4*>(C + (size_t)gr * BN + jb * 64 + tx * 4) = v;
        }
    }
}

// ---------------- CSR gather aggregation --------------------------------------
// 128-wide: one warp per dst; lane owns float4. out[d] += rs_in[d] * sum z[src].
__global__ __launch_bounds__(256)
void gather128(const float* __restrict__ z, float* __restrict__ out,
               const int* __restrict__ off, const int* __restrict__ degin,
               const int* __restrict__ adj, const float* __restrict__ rsin, int M) {
    int w = (blockIdx.x * blockDim.x + threadIdx.x) >> 5;
    if (w >= M) return;
    int lane = threadIdx.x & 31;
    int st = __ldg(off + w);
    int len = __ldg(degin + w);
    float4 acc = make_float4(0.f, 0.f, 0.f, 0.f);
    int j = 0;
    for (; j + 1 < len; j += 2) {            // 2-deep unroll for MLP
        int s0 = __ldg(adj + st + j);
        int s1 = __ldg(adj + st + j + 1);
        float4 v0 = __ldg(reinterpret_cast<const float4*>(z + (size_t)s0 * 128 + lane * 4));
        float4 v1 = __ldg(reinterpret_cast<const float4*>(z + (size_t)s1 * 128 + lane * 4));
        acc.x += v0.x + v1.x; acc.y += v0.y + v1.y;
        acc.z += v0.z + v1.z; acc.w += v0.w + v1.w;
    }
    if (j < len) {
        int s0 = __ldg(adj + st + j);
        float4 v0 = __ldg(reinterpret_cast<const float4*>(z + (size_t)s0 * 128 + lane * 4));
        acc.x += v0.x; acc.y += v0.y; acc.z += v0.z; acc.w += v0.w;
    }
    float c = __ldg(rsin + w);
    float4* hp = reinterpret_cast<float4*>(out + (size_t)w * 128 + lane * 4);
    float4 cur = *hp;
    cur.x += c * acc.x; cur.y += c * acc.y;
    cur.z += c * acc.z; cur.w += c * acc.w;
    *hp = cur;
}

// 64-wide: one warp per dst; lane owns float2.
__global__ __launch_bounds__(256)
void gather64(const float* __restrict__ z, float* __restrict__ out,
              const int* __restrict__ off, const int* __restrict__ degin,
              const int* __restrict__ adj, const float* __restrict__ rsin, int M) {
    int w = (blockIdx.x * blockDim.x + threadIdx.x) >> 5;
    if (w >= M) return;
    int lane = threadIdx.x & 31;
    int st = __ldg(off + w);
    int len = __ldg(degin + w);
    float2 acc = make_float2(0.f, 0.f);
    int j = 0;
    for (; j + 1 < len; j += 2) {
        int s0 = __ldg(adj + st + j);
        int s1 = __ldg(adj + st + j + 1);
        float2 v0 = __ldg(reinterpret_cast<const float2*>(z + (size_t)s0 * 64 + lane * 2));
        float2 v1 = __ldg(reinterpret_cast<const float2*>(z + (size_t)s1 * 64 + lane * 2));
        acc.x += v0.x + v1.x; acc.y += v0.y + v1.y;
    }
    if (j < len) {
        int s0 = __ldg(adj + st + j);
        float2 v0 = __ldg(reinterpret_cast<const float2*>(z + (size_t)s0 * 64 + lane * 2));
        acc.x += v0.x; acc.y += v0.y;
    }
    float c = __ldg(rsin + w);
    float2* hp = reinterpret_cast<float2*>(out + (size_t)w * 64 + lane * 2);
    float2 cur = *hp;
    cur.x += c * acc.x; cur.y += c * acc.y;
    *hp = cur;
}

// ---------------- elementwise epilogues --------------------------------------
__global__ void relu_bias128(float* __restrict__ h, const float* __restrict__ b1, int n) {
    int i = blockIdx.x * blockDim.x + threadIdx.x;
    if (i >= n) return;
    int c = i & 127;
    float b = __ldg(b1 + c) + __ldg(b1 + 128 + c) + __ldg(b1 + 256 + c);
    float v = h[i] + b;
    h[i] = v > 0.f ? v : 0.f;
}

__global__ void bias64(float* __restrict__ o, const float* __restrict__ b2, int n) {
    int i = blockIdx.x * blockDim.x + threadIdx.x;
    if (i >= n) return;
    int c = i & 63;
    o[i] += __ldg(b2 + c) + __ldg(b2 + 64 + c) + __ldg(b2 + 128 + c);
}

// ---------------- orchestration ----------------------------------------------
extern "C" void kernel_launch(void* const* d_in, const int* in_sizes, int n_in,
                              void* d_out, int out_size) {
    const float* x  = (const float*)d_in[0];
    const float* W1 = (const float*)d_in[1];
    const float* b1 = (const float*)d_in[2];
    const float* W2 = (const float*)d_in[3];
    const float* b2 = (const float*)d_in[4];
    const int*   ei = (const int*)d_in[5];
    float* out = (float*)d_out;

    const int M = in_sizes[0] / DIN;
    const int E = in_sizes[5] / (2 * NREL * 2);

    float *z, *h, *degf;
    int *degi, *off, *cnt, *adj, *bsum;
    cudaGetSymbolAddress((void**)&z,    g_z);
    cudaGetSymbolAddress((void**)&h,    g_h);
    cudaGetSymbolAddress((void**)&degf, g_degf);
    cudaGetSymbolAddress((void**)&degi, g_degi);
    cudaGetSymbolAddress((void**)&off,  g_off);
    cudaGetSymbolAddress((void**)&cnt,  g_cnt);
    cudaGetSymbolAddress((void**)&adj,  g_adj);
    cudaGetSymbolAddress((void**)&bsum, g_bsum);

    const int TB = 256;
    auto blocks = [](long n, int tb) { return (int)((n + tb - 1) / tb); };
    const int nblk_scan = (M + SCAN_CHUNK - 1) / SCAN_CHUNK;

    // --- zero counters / accumulators (memset nodes are graph-capturable) ----
    cudaMemsetAsync(degi, 0, (size_t)12 * M * sizeof(int));
    cudaMemsetAsync(cnt,  0, (size_t)NPAIR * M * sizeof(int));
    cudaMemsetAsync(h,    0, (size_t)M * DH * sizeof(float));
    cudaMemsetAsync(out,  0, (size_t)M * DOUT * sizeof(float));

    // --- degrees + CSR build for all 6 pairs ----------------------------------
    { dim3 g(blocks(E, TB), NPAIR); count_deg_kernel<<<g, TB>>>(ei, degi, E, M); }
    rsqrt_kernel<<<blocks((long)12 * M, TB), TB>>>(degi, degf, 12 * M);
    { dim3 g(nblk_scan, NPAIR); scanA<<<g, 256>>>(degi, off, bsum, M); }
    scanB<<<NPAIR, MAXBLK>>>(bsum, nblk_scan);
    { dim3 g(blocks(M, TB), NPAIR); scanC<<<g, TB>>>(off, bsum, M); }
    { dim3 g(blocks(E, TB), NPAIR); fill_adj_kernel<<<g, TB>>>(ei, off, cnt, adj, E, M); }

    const int gemm_grid = (M + 127) / 128;
    const int gw = blocks((long)M * 32, TB);      // gather grids (warp per node)

    // --- layer 1 ---------------------------------------------------------------
    for (int r = 0; r < NREL; r++) {
        int p = 0 * NREL + r;
        gemm_rowscale<128, 8><<<gemm_grid, 256>>>(
            x, W1 + (size_t)r * DIN * DH, degf + (size_t)(p * 2 + 0) * M, z, M);
        gather128<<<gw, TB>>>(z, h,
            off + (size_t)p * M, degi + (size_t)(p * 2 + 1) * M,
            adj + (size_t)p * E, degf + (size_t)(p * 2 + 1) * M, M);
    }
    relu_bias128<<<blocks((long)M * DH, TB), TB>>>(h, b1, M * DH);

    // --- layer 2 ---------------------------------------------------------------
    for (int r = 0; r < NREL; r++) {
        int p = 1 * NREL + r;
        gemm_rowscale<64, 4><<<gemm_grid, 256>>>(
            h, W2 + (size_t)r * DH * DOUT, degf + (size_t)(p * 2 + 0) * M, z, M);
        gather64<<<gw, TB>>>(z, out,
            off + (size_t)p * M, degi + (size_t)(p * 2 + 1) * M,
            adj + (size_t)p * E, degf + (size_t)(p * 2 + 1) * M, M);
    }
    bias64<<<blocks((long)M * DOUT, TB), TB>>>(out, b2, M * DOUT);
}